// round 11
// baseline (speedup 1.0000x reference)
#include <cuda_runtime.h>
#include <cuda_fp16.h>
#include <stdint.h>
#include <math.h>

#define N_NODES 200000
#define WDIM    512
#define HDIM    1024
#define NGRAPH  2000

// -------- scratch (__device__ globals) --------
__device__ float g_xraw[(size_t)N_NODES * WDIM];
__device__ float g_pooled[NGRAPH * WDIM];
__device__ float g_msg   [NGRAPH * HDIM];

__device__ __half g_xh [(size_t)N_NODES * WDIM];
__device__ __half g_xl [(size_t)N_NODES * WDIM];
__device__ __half g_xxh[(size_t)N_NODES * WDIM];
__device__ __half g_xxl[(size_t)N_NODES * WDIM];
__device__ __half g_th [(size_t)N_NODES * HDIM];
__device__ __half g_tl [(size_t)N_NODES * HDIM];
__device__ __half g_ph [NGRAPH * WDIM];
__device__ __half g_pl [NGRAPH * WDIM];

__device__ __half g_prew [WDIM * WDIM];
__device__ __half g_memw [WDIM * HDIM];
__device__ __half g_msgw [WDIM * HDIM];
__device__ __half g_postw[HDIM * WDIM];

__global__ void zero_pooled_kernel() {
    int i = blockIdx.x * blockDim.x + threadIdx.x;
    if (i < NGRAPH * WDIM) g_pooled[i] = 0.0f;
}

// split fp32 -> fp16 hi + fp16 lo
__global__ void split_kernel(const float* __restrict__ src,
                             __half* __restrict__ h,
                             __half* __restrict__ l, int n4)
{
    int i = blockIdx.x * blockDim.x + threadIdx.x;
    if (i >= n4) return;
    float4 v = ((const float4*)src)[i];
    __half h0 = __float2half_rn(v.x), h1 = __float2half_rn(v.y);
    __half h2 = __float2half_rn(v.z), h3 = __float2half_rn(v.w);
    __half l0 = __float2half_rn(v.x - __half2float(h0));
    __half l1 = __float2half_rn(v.y - __half2float(h1));
    __half l2 = __float2half_rn(v.z - __half2float(h2));
    __half l3 = __float2half_rn(v.w - __half2float(h3));
    ((__half2*)h)[i * 2 + 0] = __halves2half2(h0, h1);
    ((__half2*)h)[i * 2 + 1] = __halves2half2(h2, h3);
    ((__half2*)l)[i * 2 + 0] = __halves2half2(l0, l1);
    ((__half2*)l)[i * 2 + 1] = __halves2half2(l2, l3);
}

// convert fp32 -> single fp16 (weights)
__global__ void conv_kernel(const float* __restrict__ src,
                            __half* __restrict__ h, int n4)
{
    int i = blockIdx.x * blockDim.x + threadIdx.x;
    if (i >= n4) return;
    float4 v = ((const float4*)src)[i];
    ((__half2*)h)[i * 2 + 0] = __halves2half2(__float2half_rn(v.x), __float2half_rn(v.y));
    ((__half2*)h)[i * 2 + 1] = __halves2half2(__float2half_rn(v.z), __float2half_rn(v.w));
}

// ---------------------------------------------------------------
// fp16 2-product tensor-core GEMM: C = Ahi@B + Alo@B
// CTA tile 128x256x32, 512 threads (16 warps, 2x8), warp 64x32.
// cp.async 3-stage pipeline. Inner loop identical to R7.
// MODE 0: C = acc + bias                               (pre)
// MODE 1: C = gelu(acc + bias)                         (msg)
// MODE 2: th/tl = gelu(acc+bias) + scale*msg[batch[m]] (mem)
// MODE 3: y = acc + bias; C=x+y; out2=y                (post)
// ---------------------------------------------------------------
#define BM 128
#define BN 256
#define BK 32
#define ASTR 40     // halves: 80B row stride
#define BSTR 264    // halves: 528B row stride (mod 128 = 16 -> conflict-free)
#define STAGES 3
#define A_H_OFF 0
#define A_L_OFF (BM * ASTR)                 // 5120
#define B_OFF   (2 * BM * ASTR)             // 10240
#define STAGE_ELEMS (2 * BM * ASTR + BK * BSTR)   // 18688
#define SMEM_BYTES (STAGES * STAGE_ELEMS * 2)     // 112128

__device__ __forceinline__ float gelu_exact(float v) {
    return 0.5f * v * (1.0f + erff(v * 0.70710678118654752f));
}
__device__ __forceinline__ unsigned int s2u(const void* p) {
    return (unsigned int)__cvta_generic_to_shared(p);
}
__device__ __forceinline__ void cp16(unsigned int dst, const void* src, int sz) {
    asm volatile("cp.async.cg.shared.global [%0], [%1], 16, %2;"
                 :: "r"(dst), "l"(src), "r"(sz));
}

#define LDSM4(R, ADDR) asm volatile( \
    "ldmatrix.sync.aligned.m8n8.x4.shared.b16 {%0,%1,%2,%3}, [%4];" \
    : "=r"((R)[0]), "=r"((R)[1]), "=r"((R)[2]), "=r"((R)[3]) : "r"(ADDR))

#define LDSM2T(R, ADDR) asm volatile( \
    "ldmatrix.sync.aligned.m8n8.x2.trans.shared.b16 {%0,%1}, [%2];" \
    : "=r"((R)[0]), "=r"((R)[1]) : "r"(ADDR))

#define MMA_F16(D, Ar, Br) asm volatile( \
    "mma.sync.aligned.m16n8k16.row.col.f32.f16.f16.f32 " \
    "{%0,%1,%2,%3},{%4,%5,%6,%7},{%8,%9},{%0,%1,%2,%3};" \
    : "+f"((D)[0]), "+f"((D)[1]), "+f"((D)[2]), "+f"((D)[3]) \
    : "r"((Ar)[0]), "r"((Ar)[1]), "r"((Ar)[2]), "r"((Ar)[3]), \
      "r"((Br)[0]), "r"((Br)[1]))

template<int MODE>
__global__ __launch_bounds__(512, 1)
void gemm_split(const __half* __restrict__ Agh, const __half* __restrict__ Agl,
                const __half* __restrict__ Bg,
                float* __restrict__ C, int M, int N, int K,
                const float* __restrict__ bias,
                const float* __restrict__ extra,   // MODE2: g_msg, MODE3: x
                const int*   __restrict__ batch,
                const float* __restrict__ zero,
                __half* __restrict__ outh,
                __half* __restrict__ outl,
                float* __restrict__ out2)
{
    extern __shared__ __half smem[];

    const int tid  = threadIdx.x;
    const int lane = tid & 31, warp = tid >> 5;
    const int warp_m = warp >> 3;      // 0..1
    const int warp_n = warp & 7;       // 0..7
    const int bm = blockIdx.y * BM;
    const int bn = blockIdx.x * BN;

    float acc[4][4][4];
    #pragma unroll
    for (int a = 0; a < 4; a++)
        #pragma unroll
        for (int b = 0; b < 4; b++)
            #pragma unroll
            for (int c = 0; c < 4; c++) acc[a][b][c] = 0.0f;

    const int KT = K / BK;

    auto issue = [&](int s, int k0) {
        __half* base = smem + s * STAGE_ELEMS;
        {   // A hi/lo: 512 chunks each, one per thread
            int row = tid >> 2, coff = (tid & 3) * 8;
            int gm = bm + row;
            int p = (gm < M) ? 16 : 0;
            size_t go = (size_t)(p ? gm : 0) * K + k0 + coff;
            cp16(s2u(base + A_H_OFF + row * ASTR + coff), Agh + go, p);
            cp16(s2u(base + A_L_OFF + row * ASTR + coff), Agl + go, p);
        }
        #pragma unroll
        for (int i = 0; i < 2; i++) {   // B: 1024 chunks
            int c = tid + 512 * i;
            int row = c >> 5, coff = (c & 31) * 8;
            size_t go = (size_t)(k0 + row) * N + bn + coff;
            cp16(s2u(base + B_OFF + row * BSTR + coff), Bg + go, 16);
        }
    };

    auto compute = [&](int s) {
        __half* base = smem + s * STAGE_ELEMS;
        #pragma unroll
        for (int kk = 0; kk < 2; kk++) {
            unsigned int ah[4][4], al[4][4], bb[4][2];
            #pragma unroll
            for (int mt = 0; mt < 4; mt++) {
                int row = warp_m * 64 + mt * 16 + (lane & 15);
                int col = kk * 16 + (lane >> 4) * 8;
                LDSM4(ah[mt], s2u(base + A_H_OFF + row * ASTR + col));
                LDSM4(al[mt], s2u(base + A_L_OFF + row * ASTR + col));
            }
            #pragma unroll
            for (int nt = 0; nt < 4; nt++) {
                int row = kk * 16 + (lane & 15);
                int col = warp_n * 32 + nt * 8;
                LDSM2T(bb[nt], s2u(base + B_OFF + row * BSTR + col));
            }
            #pragma unroll
            for (int mt = 0; mt < 4; mt++)
                #pragma unroll
                for (int nt = 0; nt < 4; nt++) {
                    MMA_F16(acc[mt][nt], ah[mt], bb[nt]);
                    MMA_F16(acc[mt][nt], al[mt], bb[nt]);
                }
        }
    };

    // prologue: prefetch STAGES-1 stages
    #pragma unroll
    for (int s = 0; s < STAGES - 1; s++) {
        if (s < KT) issue(s, s * BK);
        asm volatile("cp.async.commit_group;");
    }

    for (int kt = 0; kt < KT; kt++) {
        asm volatile("cp.async.wait_group %0;" :: "n"(STAGES - 2));
        __syncthreads();
        compute(kt % STAGES);
        int next = kt + STAGES - 1;
        if (next < KT) issue(next % STAGES, next * BK);
        asm volatile("cp.async.commit_group;");
    }

    // ---------------- epilogue ----------------
    float scale = 1.0f;
    if (MODE == 2) scale = expf(zero[0]);

    #pragma unroll
    for (int mt = 0; mt < 4; mt++) {
        const int rbase = bm + warp_m * 64 + mt * 16 + (lane >> 2);
        #pragma unroll
        for (int half = 0; half < 2; half++) {
            const int row = rbase + half * 8;
            if (row >= M) continue;
            int g = 0;
            if (MODE == 2) g = batch[row];
            #pragma unroll
            for (int nt = 0; nt < 4; nt++) {
                const int col = bn + warp_n * 32 + nt * 8 + (lane & 3) * 2;
                float v0 = acc[mt][nt][half * 2 + 0] + bias[col];
                float v1 = acc[mt][nt][half * 2 + 1] + bias[col + 1];
                if (MODE == 1 || MODE == 2) {
                    v0 = gelu_exact(v0);
                    v1 = gelu_exact(v1);
                }
                if (MODE == 2) {
                    float2 mv = *(const float2*)(extra + (size_t)g * N + col);
                    v0 += scale * mv.x;
                    v1 += scale * mv.y;
                    __half h0 = __float2half_rn(v0);
                    __half h1 = __float2half_rn(v1);
                    __half l0 = __float2half_rn(v0 - __half2float(h0));
                    __half l1 = __float2half_rn(v1 - __half2float(h1));
                    *(__half2*)(outh + (size_t)row * N + col) = __halves2half2(h0, h1);
                    *(__half2*)(outl + (size_t)row * N + col) = __halves2half2(l0, l1);
                } else if (MODE == 3) {
                    float2 xv = *(const float2*)(extra + (size_t)row * N + col);
                    *(float2*)(out2 + (size_t)row * N + col) = make_float2(v0, v1);
                    *(float2*)(C + (size_t)row * N + col) =
                        make_float2(xv.x + v0, xv.y + v1);
                } else {
                    *(float2*)(C + (size_t)row * N + col) = make_float2(v0, v1);
                }
            }
        }
    }
}

// ---------------------------------------------------------------
// LayerNorm + segment pooling; writes xx as fp16 hi/lo split.
// ---------------------------------------------------------------
#define LN_ROWS 32
__global__ __launch_bounds__(128)
void ln_pool_kernel(const float* __restrict__ xraw,
                    __half* __restrict__ xxh,
                    __half* __restrict__ xxl,
                    float* __restrict__ pooled, const int* __restrict__ batch)
{
    __shared__ float shs[4], shs2[4];
    const int tid  = threadIdx.x;
    const int lane = tid & 31, warp = tid >> 5;
    const int row0 = blockIdx.x * LN_ROWS;

    float acc0 = 0.f, acc1 = 0.f, acc2 = 0.f, acc3 = 0.f;
    int cur_g = batch[row0];

    for (int r = 0; r < LN_ROWS; r++) {
        const int row = row0 + r;
        float4 v = *(const float4*)(xraw + (size_t)row * WDIM + tid * 4);
        float s  = v.x + v.y + v.z + v.w;
        float s2 = v.x * v.x + v.y * v.y + v.z * v.z + v.w * v.w;
        #pragma unroll
        for (int o = 16; o > 0; o >>= 1) {
            s  += __shfl_xor_sync(0xffffffffu, s,  o);
            s2 += __shfl_xor_sync(0xffffffffu, s2, o);
        }
        if (lane == 0) { shs[warp] = s; shs2[warp] = s2; }
        __syncthreads();
        float sum  = shs[0] + shs[1] + shs[2] + shs[3];
        float sum2 = shs2[0] + shs2[1] + shs2[2] + shs2[3];
        __syncthreads();

        const float mu  = sum * (1.0f / WDIM);
        const float var = sum2 * (1.0f / WDIM) - mu * mu;
        const float rs  = rsqrtf(var + 1e-5f);
        v.x = (v.x - mu) * rs; v.y = (v.y - mu) * rs;
        v.z = (v.z - mu) * rs; v.w = (v.w - mu) * rs;

        __half h0 = __float2half_rn(v.x), h1 = __float2half_rn(v.y);
        __half h2 = __float2half_rn(v.z), h3 = __float2half_rn(v.w);
        __half l0 = __float2half_rn(v.x - __half2float(h0));
        __half l1 = __float2half_rn(v.y - __half2float(h1));
        __half l2 = __float2half_rn(v.z - __half2float(h2));
        __half l3 = __float2half_rn(v.w - __half2float(h3));
        size_t o = (size_t)row * WDIM + tid * 4;
        *(__half2*)(xxh + o + 0) = __halves2half2(h0, h1);
        *(__half2*)(xxh + o + 2) = __halves2half2(h2, h3);
        *(__half2*)(xxl + o + 0) = __halves2half2(l0, l1);
        *(__half2*)(xxl + o + 2) = __halves2half2(l2, l3);

        const int g = batch[row];
        if (g != cur_g) {
            float* p = pooled + (size_t)cur_g * WDIM + tid * 4;
            atomicAdd(p + 0, acc0); atomicAdd(p + 1, acc1);
            atomicAdd(p + 2, acc2); atomicAdd(p + 3, acc3);
            acc0 = acc1 = acc2 = acc3 = 0.f;
            cur_g = g;
        }
        acc0 += v.x; acc1 += v.y; acc2 += v.z; acc3 += v.w;
    }
    float* p = pooled + (size_t)cur_g * WDIM + tid * 4;
    atomicAdd(p + 0, acc0); atomicAdd(p + 1, acc1);
    atomicAdd(p + 2, acc2); atomicAdd(p + 3, acc3);
}

// ---------------------------------------------------------------
extern "C" void kernel_launch(void* const* d_in, const int* in_sizes, int n_in,
                              void* d_out, int out_size)
{
    const float* x      = (const float*)d_in[0];
    const int*   batch  = (const int*)  d_in[1];
    const float* pre_w  = (const float*)d_in[2];
    const float* pre_b  = (const float*)d_in[3];
    const float* mem_w  = (const float*)d_in[4];
    const float* mem_b  = (const float*)d_in[5];
    const float* msg_w  = (const float*)d_in[6];
    const float* msg_b  = (const float*)d_in[7];
    const float* post_w = (const float*)d_in[8];
    const float* post_b = (const float*)d_in[9];
    const float* zero   = (const float*)d_in[10];

    float* out1 = (float*)d_out;
    float* out2 = out1 + (size_t)N_NODES * WDIM;

    float *xraw, *pooled, *msg;
    __half *xh, *xl, *xxh, *xxl, *th, *tl, *ph, *pl;
    __half *prew, *memw, *msgw, *postw;
    cudaGetSymbolAddress((void**)&xraw,   g_xraw);
    cudaGetSymbolAddress((void**)&pooled, g_pooled);
    cudaGetSymbolAddress((void**)&msg,    g_msg);
    cudaGetSymbolAddress((void**)&xh,  g_xh);   cudaGetSymbolAddress((void**)&xl,  g_xl);
    cudaGetSymbolAddress((void**)&xxh, g_xxh);  cudaGetSymbolAddress((void**)&xxl, g_xxl);
    cudaGetSymbolAddress((void**)&th,  g_th);   cudaGetSymbolAddress((void**)&tl,  g_tl);
    cudaGetSymbolAddress((void**)&ph,  g_ph);   cudaGetSymbolAddress((void**)&pl,  g_pl);
    cudaGetSymbolAddress((void**)&prew,  g_prew);
    cudaGetSymbolAddress((void**)&memw,  g_memw);
    cudaGetSymbolAddress((void**)&msgw,  g_msgw);
    cudaGetSymbolAddress((void**)&postw, g_postw);

    cudaFuncSetAttribute(gemm_split<0>, cudaFuncAttributeMaxDynamicSharedMemorySize, SMEM_BYTES);
    cudaFuncSetAttribute(gemm_split<1>, cudaFuncAttributeMaxDynamicSharedMemorySize, SMEM_BYTES);
    cudaFuncSetAttribute(gemm_split<2>, cudaFuncAttributeMaxDynamicSharedMemorySize, SMEM_BYTES);
    cudaFuncSetAttribute(gemm_split<3>, cudaFuncAttributeMaxDynamicSharedMemorySize, SMEM_BYTES);

    const dim3 blk(512);
    const int gy = (N_NODES + BM - 1) / BM;           // 1563

    // 0. splits + conversions + zero
    zero_pooled_kernel<<<(NGRAPH * WDIM + 255) / 256, 256>>>();
    {
        int n4 = (int)((size_t)N_NODES * WDIM / 4);
        split_kernel<<<(n4 + 255) / 256, 256>>>(x, xh, xl, n4);
        conv_kernel<<<(WDIM * WDIM / 4 + 255) / 256, 256>>>(pre_w,  prew,  WDIM * WDIM / 4);
        conv_kernel<<<(WDIM * HDIM / 4 + 255) / 256, 256>>>(mem_w,  memw,  WDIM * HDIM / 4);
        conv_kernel<<<(WDIM * HDIM / 4 + 255) / 256, 256>>>(msg_w,  msgw,  WDIM * HDIM / 4);
        conv_kernel<<<(HDIM * WDIM / 4 + 255) / 256, 256>>>(post_w, postw, HDIM * WDIM / 4);
    }

    // 1. pre GEMM: xraw = x @ pre_w + pre_b
    gemm_split<0><<<dim3(WDIM / BN, gy), blk, SMEM_BYTES>>>(
        xh, xl, prew, xraw, N_NODES, WDIM, WDIM, pre_b,
        nullptr, nullptr, nullptr, nullptr, nullptr, nullptr);

    // 2. LayerNorm + segment pooling (-> xxh/xxl split, pooled fp32)
    ln_pool_kernel<<<N_NODES / LN_ROWS, 128>>>(xraw, xxh, xxl, pooled, batch);

    // 3. split pooled
    split_kernel<<<(NGRAPH * WDIM / 4 + 255) / 256, 256>>>(pooled, ph, pl, NGRAPH * WDIM / 4);

    // 4. msg GEMM: msg = gelu(pooled @ msg_w + msg_b)
    gemm_split<1><<<dim3(HDIM / BN, (NGRAPH + BM - 1) / BM), blk, SMEM_BYTES>>>(
        ph, pl, msgw, msg, NGRAPH, HDIM, WDIM, msg_b,
        nullptr, nullptr, nullptr, nullptr, nullptr, nullptr);

    // 5. mem GEMM fused: t(h/l) = gelu(xx @ mem_w + mem_b) + exp(zero)*msg[batch]
    gemm_split<2><<<dim3(HDIM / BN, gy), blk, SMEM_BYTES>>>(
        xxh, xxl, memw, nullptr, N_NODES, HDIM, WDIM, mem_b,
        msg, batch, zero, th, tl, nullptr);

    // 6. post GEMM fused: y = t @ post_w + post_b; out1 = x + y; out2 = y
    gemm_split<3><<<dim3(WDIM / BN, gy), blk, SMEM_BYTES>>>(
        th, tl, postw, out1, N_NODES, WDIM, HDIM, post_b,
        x, nullptr, nullptr, nullptr, nullptr, out2);
}

// round 12
// speedup vs baseline: 1.2618x; 1.2618x over previous
#include <cuda_runtime.h>
#include <cuda_fp16.h>
#include <stdint.h>
#include <math.h>

#define N_NODES 200000
#define WDIM    512
#define HDIM    1024
#define NGRAPH  2000

// -------- scratch (__device__ globals) --------
__device__ float g_xraw[(size_t)N_NODES * WDIM];
__device__ float g_pooled[NGRAPH * WDIM];
__device__ float g_msg   [NGRAPH * HDIM];

__device__ __half g_xh [(size_t)N_NODES * WDIM];
__device__ __half g_xl [(size_t)N_NODES * WDIM];
__device__ __half g_xxh[(size_t)N_NODES * WDIM];
__device__ __half g_xxl[(size_t)N_NODES * WDIM];
__device__ __half g_th [(size_t)N_NODES * HDIM];
__device__ __half g_ph [NGRAPH * WDIM];
__device__ __half g_pl [NGRAPH * WDIM];

__device__ __half g_prew [WDIM * WDIM];
__device__ __half g_memw [WDIM * HDIM];
__device__ __half g_msgw [WDIM * HDIM];
__device__ __half g_postw[HDIM * WDIM];

__global__ void zero_pooled_kernel() {
    int i = blockIdx.x * blockDim.x + threadIdx.x;
    if (i < NGRAPH * WDIM) g_pooled[i] = 0.0f;
}

// split fp32 -> fp16 hi + fp16 lo
__global__ void split_kernel(const float* __restrict__ src,
                             __half* __restrict__ h,
                             __half* __restrict__ l, int n4)
{
    int i = blockIdx.x * blockDim.x + threadIdx.x;
    if (i >= n4) return;
    float4 v = ((const float4*)src)[i];
    __half h0 = __float2half_rn(v.x), h1 = __float2half_rn(v.y);
    __half h2 = __float2half_rn(v.z), h3 = __float2half_rn(v.w);
    __half l0 = __float2half_rn(v.x - __half2float(h0));
    __half l1 = __float2half_rn(v.y - __half2float(h1));
    __half l2 = __float2half_rn(v.z - __half2float(h2));
    __half l3 = __float2half_rn(v.w - __half2float(h3));
    ((__half2*)h)[i * 2 + 0] = __halves2half2(h0, h1);
    ((__half2*)h)[i * 2 + 1] = __halves2half2(h2, h3);
    ((__half2*)l)[i * 2 + 0] = __halves2half2(l0, l1);
    ((__half2*)l)[i * 2 + 1] = __halves2half2(l2, l3);
}

// convert fp32 -> single fp16 (weights)
__global__ void conv_kernel(const float* __restrict__ src,
                            __half* __restrict__ h, int n4)
{
    int i = blockIdx.x * blockDim.x + threadIdx.x;
    if (i >= n4) return;
    float4 v = ((const float4*)src)[i];
    ((__half2*)h)[i * 2 + 0] = __halves2half2(__float2half_rn(v.x), __float2half_rn(v.y));
    ((__half2*)h)[i * 2 + 1] = __halves2half2(__float2half_rn(v.z), __float2half_rn(v.w));
}

// ---------------------------------------------------------------
// fp16 tensor-core GEMM: C = Ahi@B (+ Alo@B if NPROD==2)
// 128x128x32 tile, 256 threads (8 warps 2x4), warp 64x32,
// cp.async 3-stage pipeline, 2 CTAs/SM.  (R7 structure.)
// MODE 0: C = acc + bias                               (pre)
// MODE 1: C = gelu(acc + bias)                         (msg)
// MODE 2: th = gelu(acc+bias) + scale*msg[batch[m]]    (mem, single fp16 out)
// MODE 3: y = acc + bias; C=x+y; out2=y                (post)
// ---------------------------------------------------------------
#define BM 128
#define BN 128
#define BK 32
#define ASTR 40     // halves: 80B row stride
#define BSTR 136    // halves: 272B row stride
#define STAGES 3
#define A_H_OFF 0
#define A_L_OFF (BM * ASTR)                 // 5120
#define B_OFF   (2 * BM * ASTR)             // 10240
#define STAGE_ELEMS (2 * BM * ASTR + BK * BSTR)   // 14592
#define SMEM_BYTES (STAGES * STAGE_ELEMS * 2)     // 87552

__device__ __forceinline__ float gelu_exact(float v) {
    return 0.5f * v * (1.0f + erff(v * 0.70710678118654752f));
}
__device__ __forceinline__ unsigned int s2u(const void* p) {
    return (unsigned int)__cvta_generic_to_shared(p);
}
__device__ __forceinline__ void cp16(unsigned int dst, const void* src, int sz) {
    asm volatile("cp.async.cg.shared.global [%0], [%1], 16, %2;"
                 :: "r"(dst), "l"(src), "r"(sz));
}

#define LDSM4(R, ADDR) asm volatile( \
    "ldmatrix.sync.aligned.m8n8.x4.shared.b16 {%0,%1,%2,%3}, [%4];" \
    : "=r"((R)[0]), "=r"((R)[1]), "=r"((R)[2]), "=r"((R)[3]) : "r"(ADDR))

#define LDSM2T(R, ADDR) asm volatile( \
    "ldmatrix.sync.aligned.m8n8.x2.trans.shared.b16 {%0,%1}, [%2];" \
    : "=r"((R)[0]), "=r"((R)[1]) : "r"(ADDR))

#define MMA_F16(D, Ar, Br) asm volatile( \
    "mma.sync.aligned.m16n8k16.row.col.f32.f16.f16.f32 " \
    "{%0,%1,%2,%3},{%4,%5,%6,%7},{%8,%9},{%0,%1,%2,%3};" \
    : "+f"((D)[0]), "+f"((D)[1]), "+f"((D)[2]), "+f"((D)[3]) \
    : "r"((Ar)[0]), "r"((Ar)[1]), "r"((Ar)[2]), "r"((Ar)[3]), \
      "r"((Br)[0]), "r"((Br)[1]))

template<int MODE, int NPROD>
__global__ __launch_bounds__(256, 2)
void gemm_split(const __half* __restrict__ Agh, const __half* __restrict__ Agl,
                const __half* __restrict__ Bg,
                float* __restrict__ C, int M, int N, int K,
                const float* __restrict__ bias,
                const float* __restrict__ extra,   // MODE2: g_msg, MODE3: x
                const int*   __restrict__ batch,
                const float* __restrict__ zero,
                __half* __restrict__ outh,
                float* __restrict__ out2)
{
    extern __shared__ __half smem[];

    const int tid  = threadIdx.x;
    const int lane = tid & 31, warp = tid >> 5;
    const int warp_m = warp >> 2;
    const int warp_n = warp & 3;
    const int bm = blockIdx.y * BM;
    const int bn = blockIdx.x * BN;

    float acc[4][4][4];
    #pragma unroll
    for (int a = 0; a < 4; a++)
        #pragma unroll
        for (int b = 0; b < 4; b++)
            #pragma unroll
            for (int c = 0; c < 4; c++) acc[a][b][c] = 0.0f;

    const int KT = K / BK;

    auto issue = [&](int s, int k0) {
        __half* base = smem + s * STAGE_ELEMS;
        #pragma unroll
        for (int i = 0; i < 2; i++) {
            int c = tid + 256 * i;
            int row = c >> 2, coff = (c & 3) * 8;
            int gm = bm + row;
            int p = (gm < M) ? 16 : 0;
            size_t go = (size_t)(p ? gm : 0) * K + k0 + coff;
            cp16(s2u(base + A_H_OFF + row * ASTR + coff), Agh + go, p);
            if (NPROD == 2)
                cp16(s2u(base + A_L_OFF + row * ASTR + coff), Agl + go, p);
        }
        #pragma unroll
        for (int i = 0; i < 2; i++) {
            int c = tid + 256 * i;
            int row = c >> 4, coff = (c & 15) * 8;
            size_t go = (size_t)(k0 + row) * N + bn + coff;
            cp16(s2u(base + B_OFF + row * BSTR + coff), Bg + go, 16);
        }
    };

    auto compute = [&](int s) {
        __half* base = smem + s * STAGE_ELEMS;
        #pragma unroll
        for (int kk = 0; kk < 2; kk++) {
            unsigned int ah[4][4], al[4][4], bb[4][2];
            #pragma unroll
            for (int mt = 0; mt < 4; mt++) {
                int row = warp_m * 64 + mt * 16 + (lane & 15);
                int col = kk * 16 + (lane >> 4) * 8;
                LDSM4(ah[mt], s2u(base + A_H_OFF + row * ASTR + col));
                if (NPROD == 2)
                    LDSM4(al[mt], s2u(base + A_L_OFF + row * ASTR + col));
            }
            #pragma unroll
            for (int nt = 0; nt < 4; nt++) {
                int row = kk * 16 + (lane & 15);
                int col = warp_n * 32 + nt * 8;
                LDSM2T(bb[nt], s2u(base + B_OFF + row * BSTR + col));
            }
            #pragma unroll
            for (int mt = 0; mt < 4; mt++)
                #pragma unroll
                for (int nt = 0; nt < 4; nt++) {
                    MMA_F16(acc[mt][nt], ah[mt], bb[nt]);
                    if (NPROD == 2)
                        MMA_F16(acc[mt][nt], al[mt], bb[nt]);
                }
        }
    };

    // prologue: prefetch STAGES-1 stages
    #pragma unroll
    for (int s = 0; s < STAGES - 1; s++) {
        if (s < KT) issue(s, s * BK);
        asm volatile("cp.async.commit_group;");
    }

    for (int kt = 0; kt < KT; kt++) {
        asm volatile("cp.async.wait_group %0;" :: "n"(STAGES - 2));
        __syncthreads();
        compute(kt % STAGES);
        int next = kt + STAGES - 1;
        if (next < KT) issue(next % STAGES, next * BK);
        asm volatile("cp.async.commit_group;");
    }

    // ---------------- epilogue ----------------
    float scale = 1.0f;
    if (MODE == 2) scale = expf(zero[0]);

    #pragma unroll
    for (int mt = 0; mt < 4; mt++) {
        const int rbase = bm + warp_m * 64 + mt * 16 + (lane >> 2);
        #pragma unroll
        for (int half = 0; half < 2; half++) {
            const int row = rbase + half * 8;
            if (row >= M) continue;
            int g = 0;
            if (MODE == 2) g = batch[row];
            #pragma unroll
            for (int nt = 0; nt < 4; nt++) {
                const int col = bn + warp_n * 32 + nt * 8 + (lane & 3) * 2;
                float v0 = acc[mt][nt][half * 2 + 0] + bias[col];
                float v1 = acc[mt][nt][half * 2 + 1] + bias[col + 1];
                if (MODE == 1 || MODE == 2) {
                    v0 = gelu_exact(v0);
                    v1 = gelu_exact(v1);
                }
                if (MODE == 2) {
                    float2 mv = *(const float2*)(extra + (size_t)g * N + col);
                    v0 += scale * mv.x;
                    v1 += scale * mv.y;
                    // single fp16 output (post GEMM uses 1-product A)
                    *(__half2*)(outh + (size_t)row * N + col) =
                        __halves2half2(__float2half_rn(v0), __float2half_rn(v1));
                } else if (MODE == 3) {
                    float2 xv = *(const float2*)(extra + (size_t)row * N + col);
                    *(float2*)(out2 + (size_t)row * N + col) = make_float2(v0, v1);
                    *(float2*)(C + (size_t)row * N + col) =
                        make_float2(xv.x + v0, xv.y + v1);
                } else {
                    *(float2*)(C + (size_t)row * N + col) = make_float2(v0, v1);
                }
            }
        }
    }
}

// ---------------------------------------------------------------
// LayerNorm + segment pooling; writes xx as fp16 hi/lo split.
// ---------------------------------------------------------------
#define LN_ROWS 32
__global__ __launch_bounds__(128)
void ln_pool_kernel(const float* __restrict__ xraw,
                    __half* __restrict__ xxh,
                    __half* __restrict__ xxl,
                    float* __restrict__ pooled, const int* __restrict__ batch)
{
    __shared__ float shs[4], shs2[4];
    const int tid  = threadIdx.x;
    const int lane = tid & 31, warp = tid >> 5;
    const int row0 = blockIdx.x * LN_ROWS;

    float acc0 = 0.f, acc1 = 0.f, acc2 = 0.f, acc3 = 0.f;
    int cur_g = batch[row0];

    for (int r = 0; r < LN_ROWS; r++) {
        const int row = row0 + r;
        float4 v = *(const float4*)(xraw + (size_t)row * WDIM + tid * 4);
        float s  = v.x + v.y + v.z + v.w;
        float s2 = v.x * v.x + v.y * v.y + v.z * v.z + v.w * v.w;
        #pragma unroll
        for (int o = 16; o > 0; o >>= 1) {
            s  += __shfl_xor_sync(0xffffffffu, s,  o);
            s2 += __shfl_xor_sync(0xffffffffu, s2, o);
        }
        if (lane == 0) { shs[warp] = s; shs2[warp] = s2; }
        __syncthreads();
        float sum  = shs[0] + shs[1] + shs[2] + shs[3];
        float sum2 = shs2[0] + shs2[1] + shs2[2] + shs2[3];
        __syncthreads();

        const float mu  = sum * (1.0f / WDIM);
        const float var = sum2 * (1.0f / WDIM) - mu * mu;
        const float rs  = rsqrtf(var + 1e-5f);
        v.x = (v.x - mu) * rs; v.y = (v.y - mu) * rs;
        v.z = (v.z - mu) * rs; v.w = (v.w - mu) * rs;

        __half h0 = __float2half_rn(v.x), h1 = __float2half_rn(v.y);
        __half h2 = __float2half_rn(v.z), h3 = __float2half_rn(v.w);
        __half l0 = __float2half_rn(v.x - __half2float(h0));
        __half l1 = __float2half_rn(v.y - __half2float(h1));
        __half l2 = __float2half_rn(v.z - __half2float(h2));
        __half l3 = __float2half_rn(v.w - __half2float(h3));
        size_t o = (size_t)row * WDIM + tid * 4;
        *(__half2*)(xxh + o + 0) = __halves2half2(h0, h1);
        *(__half2*)(xxh + o + 2) = __halves2half2(h2, h3);
        *(__half2*)(xxl + o + 0) = __halves2half2(l0, l1);
        *(__half2*)(xxl + o + 2) = __halves2half2(l2, l3);

        const int g = batch[row];
        if (g != cur_g) {
            float* p = pooled + (size_t)cur_g * WDIM + tid * 4;
            atomicAdd(p + 0, acc0); atomicAdd(p + 1, acc1);
            atomicAdd(p + 2, acc2); atomicAdd(p + 3, acc3);
            acc0 = acc1 = acc2 = acc3 = 0.f;
            cur_g = g;
        }
        acc0 += v.x; acc1 += v.y; acc2 += v.z; acc3 += v.w;
    }
    float* p = pooled + (size_t)cur_g * WDIM + tid * 4;
    atomicAdd(p + 0, acc0); atomicAdd(p + 1, acc1);
    atomicAdd(p + 2, acc2); atomicAdd(p + 3, acc3);
}

// ---------------------------------------------------------------
extern "C" void kernel_launch(void* const* d_in, const int* in_sizes, int n_in,
                              void* d_out, int out_size)
{
    const float* x      = (const float*)d_in[0];
    const int*   batch  = (const int*)  d_in[1];
    const float* pre_w  = (const float*)d_in[2];
    const float* pre_b  = (const float*)d_in[3];
    const float* mem_w  = (const float*)d_in[4];
    const float* mem_b  = (const float*)d_in[5];
    const float* msg_w  = (const float*)d_in[6];
    const float* msg_b  = (const float*)d_in[7];
    const float* post_w = (const float*)d_in[8];
    const float* post_b = (const float*)d_in[9];
    const float* zero   = (const float*)d_in[10];

    float* out1 = (float*)d_out;
    float* out2 = out1 + (size_t)N_NODES * WDIM;

    float *xraw, *pooled, *msg;
    __half *xh, *xl, *xxh, *xxl, *th, *ph, *pl;
    __half *prew, *memw, *msgw, *postw;
    cudaGetSymbolAddress((void**)&xraw,   g_xraw);
    cudaGetSymbolAddress((void**)&pooled, g_pooled);
    cudaGetSymbolAddress((void**)&msg,    g_msg);
    cudaGetSymbolAddress((void**)&xh,  g_xh);   cudaGetSymbolAddress((void**)&xl,  g_xl);
    cudaGetSymbolAddress((void**)&xxh, g_xxh);  cudaGetSymbolAddress((void**)&xxl, g_xxl);
    cudaGetSymbolAddress((void**)&th,  g_th);
    cudaGetSymbolAddress((void**)&ph,  g_ph);   cudaGetSymbolAddress((void**)&pl,  g_pl);
    cudaGetSymbolAddress((void**)&prew,  g_prew);
    cudaGetSymbolAddress((void**)&memw,  g_memw);
    cudaGetSymbolAddress((void**)&msgw,  g_msgw);
    cudaGetSymbolAddress((void**)&postw, g_postw);

    cudaFuncSetAttribute((const void*)gemm_split<0,2>, cudaFuncAttributeMaxDynamicSharedMemorySize, SMEM_BYTES);
    cudaFuncSetAttribute((const void*)gemm_split<1,2>, cudaFuncAttributeMaxDynamicSharedMemorySize, SMEM_BYTES);
    cudaFuncSetAttribute((const void*)gemm_split<2,2>, cudaFuncAttributeMaxDynamicSharedMemorySize, SMEM_BYTES);
    cudaFuncSetAttribute((const void*)gemm_split<3,1>, cudaFuncAttributeMaxDynamicSharedMemorySize, SMEM_BYTES);

    const dim3 blk(256);
    const int gy = (N_NODES + BM - 1) / BM;           // 1563

    // 0. splits + conversions + zero
    zero_pooled_kernel<<<(NGRAPH * WDIM + 255) / 256, 256>>>();
    {
        int n4 = (int)((size_t)N_NODES * WDIM / 4);
        split_kernel<<<(n4 + 255) / 256, 256>>>(x, xh, xl, n4);
        conv_kernel<<<(WDIM * WDIM / 4 + 255) / 256, 256>>>(pre_w,  prew,  WDIM * WDIM / 4);
        conv_kernel<<<(WDIM * HDIM / 4 + 255) / 256, 256>>>(mem_w,  memw,  WDIM * HDIM / 4);
        conv_kernel<<<(WDIM * HDIM / 4 + 255) / 256, 256>>>(msg_w,  msgw,  WDIM * HDIM / 4);
        conv_kernel<<<(HDIM * WDIM / 4 + 255) / 256, 256>>>(post_w, postw, HDIM * WDIM / 4);
    }

    // 1. pre GEMM: xraw = x @ pre_w + pre_b   (2-product)
    gemm_split<0,2><<<dim3(WDIM / BN, gy), blk, SMEM_BYTES>>>(
        xh, xl, prew, xraw, N_NODES, WDIM, WDIM, pre_b,
        nullptr, nullptr, nullptr, nullptr, nullptr);

    // 2. LayerNorm + segment pooling (-> xxh/xxl split, pooled fp32)
    ln_pool_kernel<<<N_NODES / LN_ROWS, 128>>>(xraw, xxh, xxl, pooled, batch);

    // 3. split pooled
    split_kernel<<<(NGRAPH * WDIM / 4 + 255) / 256, 256>>>(pooled, ph, pl, NGRAPH * WDIM / 4);

    // 4. msg GEMM: msg = gelu(pooled @ msg_w + msg_b)   (2-product)
    gemm_split<1,2><<<dim3(HDIM / BN, (NGRAPH + BM - 1) / BM), blk, SMEM_BYTES>>>(
        ph, pl, msgw, msg, NGRAPH, HDIM, WDIM, msg_b,
        nullptr, nullptr, nullptr, nullptr, nullptr);

    // 5. mem GEMM fused: th = gelu(xx @ mem_w + mem_b) + exp(zero)*msg[batch]
    //    (2-product inputs, single fp16 output)
    gemm_split<2,2><<<dim3(HDIM / BN, gy), blk, SMEM_BYTES>>>(
        xxh, xxl, memw, nullptr, N_NODES, HDIM, WDIM, mem_b,
        msg, batch, zero, th, nullptr);

    // 6. post GEMM (1-product): y = t @ post_w + post_b; out1 = x + y; out2 = y
    gemm_split<3,1><<<dim3(WDIM / BN, gy), blk, SMEM_BYTES>>>(
        th, nullptr, postw, out1, N_NODES, WDIM, HDIM, post_b,
        x, nullptr, nullptr, nullptr, out2);
}

// round 13
// speedup vs baseline: 1.6552x; 1.3118x over previous
#include <cuda_runtime.h>
#include <cuda_fp16.h>
#include <stdint.h>
#include <math.h>

#define N_NODES 200000
#define WDIM    512
#define HDIM    1024
#define NGRAPH  2000

// -------- scratch (__device__ globals) --------
__device__ float g_xraw[(size_t)N_NODES * WDIM];
__device__ float g_pooled[NGRAPH * WDIM];
__device__ float g_msg   [NGRAPH * HDIM];

__device__ __half g_xh [(size_t)N_NODES * WDIM];
__device__ __half g_xxh[(size_t)N_NODES * WDIM];
__device__ __half g_th [(size_t)N_NODES * HDIM];
__device__ __half g_ph [NGRAPH * WDIM];
__device__ __half g_pl [NGRAPH * WDIM];

__device__ __half g_prew [WDIM * WDIM];
__device__ __half g_memw [WDIM * HDIM];
__device__ __half g_msgw [WDIM * HDIM];
__device__ __half g_postw[HDIM * WDIM];

__global__ void zero_pooled_kernel() {
    int i = blockIdx.x * blockDim.x + threadIdx.x;
    if (i < NGRAPH * WDIM) g_pooled[i] = 0.0f;
}

// split fp32 -> fp16 hi + fp16 lo
__global__ void split_kernel(const float* __restrict__ src,
                             __half* __restrict__ h,
                             __half* __restrict__ l, int n4)
{
    int i = blockIdx.x * blockDim.x + threadIdx.x;
    if (i >= n4) return;
    float4 v = ((const float4*)src)[i];
    __half h0 = __float2half_rn(v.x), h1 = __float2half_rn(v.y);
    __half h2 = __float2half_rn(v.z), h3 = __float2half_rn(v.w);
    __half l0 = __float2half_rn(v.x - __half2float(h0));
    __half l1 = __float2half_rn(v.y - __half2float(h1));
    __half l2 = __float2half_rn(v.z - __half2float(h2));
    __half l3 = __float2half_rn(v.w - __half2float(h3));
    ((__half2*)h)[i * 2 + 0] = __halves2half2(h0, h1);
    ((__half2*)h)[i * 2 + 1] = __halves2half2(h2, h3);
    ((__half2*)l)[i * 2 + 0] = __halves2half2(l0, l1);
    ((__half2*)l)[i * 2 + 1] = __halves2half2(l2, l3);
}

// convert fp32 -> single fp16
__global__ void conv_kernel(const float* __restrict__ src,
                            __half* __restrict__ h, int n4)
{
    int i = blockIdx.x * blockDim.x + threadIdx.x;
    if (i >= n4) return;
    float4 v = ((const float4*)src)[i];
    ((__half2*)h)[i * 2 + 0] = __halves2half2(__float2half_rn(v.x), __float2half_rn(v.y));
    ((__half2*)h)[i * 2 + 1] = __halves2half2(__float2half_rn(v.z), __float2half_rn(v.w));
}

// ---------------------------------------------------------------
// fp16 tensor-core GEMM: C = Ahi@B (+ Alo@B if NPROD==2)
// 128x128x32 tile, 256 threads (8 warps 2x4), warp 64x32,
// cp.async 3-stage pipeline, 2 CTAs/SM. smem layout depends on NPROD.
// MODE 0: C = acc + bias                               (pre)
// MODE 1: C = gelu(acc + bias)                         (msg)
// MODE 2: th = gelu(acc+bias) + scale*msg[batch[m]]    (mem, fp16 out)
// MODE 3: y = acc + bias; C=x+y; out2=y                (post)
// ---------------------------------------------------------------
#define BM 128
#define BN 128
#define BK 32
#define ASTR 40     // halves: 80B row stride
#define BSTR 136    // halves: 272B row stride
#define STAGES 3

#define STAGE_ELEMS_N(np) (((np) == 2 ? 2 : 1) * BM * ASTR + BK * BSTR)
#define SMEM_BYTES_N(np)  (STAGES * STAGE_ELEMS_N(np) * 2)

__device__ __forceinline__ float gelu_exact(float v) {
    return 0.5f * v * (1.0f + erff(v * 0.70710678118654752f));
}
__device__ __forceinline__ unsigned int s2u(const void* p) {
    return (unsigned int)__cvta_generic_to_shared(p);
}
__device__ __forceinline__ void cp16(unsigned int dst, const void* src, int sz) {
    asm volatile("cp.async.cg.shared.global [%0], [%1], 16, %2;"
                 :: "r"(dst), "l"(src), "r"(sz));
}

#define LDSM4(R, ADDR) asm volatile( \
    "ldmatrix.sync.aligned.m8n8.x4.shared.b16 {%0,%1,%2,%3}, [%4];" \
    : "=r"((R)[0]), "=r"((R)[1]), "=r"((R)[2]), "=r"((R)[3]) : "r"(ADDR))

#define LDSM2T(R, ADDR) asm volatile( \
    "ldmatrix.sync.aligned.m8n8.x2.trans.shared.b16 {%0,%1}, [%2];" \
    : "=r"((R)[0]), "=r"((R)[1]) : "r"(ADDR))

#define MMA_F16(D, Ar, Br) asm volatile( \
    "mma.sync.aligned.m16n8k16.row.col.f32.f16.f16.f32 " \
    "{%0,%1,%2,%3},{%4,%5,%6,%7},{%8,%9},{%0,%1,%2,%3};" \
    : "+f"((D)[0]), "+f"((D)[1]), "+f"((D)[2]), "+f"((D)[3]) \
    : "r"((Ar)[0]), "r"((Ar)[1]), "r"((Ar)[2]), "r"((Ar)[3]), \
      "r"((Br)[0]), "r"((Br)[1]))

template<int MODE, int NPROD>
__global__ __launch_bounds__(256, 2)
void gemm_split(const __half* __restrict__ Agh, const __half* __restrict__ Agl,
                const __half* __restrict__ Bg,
                float* __restrict__ C, int M, int N, int K,
                const float* __restrict__ bias,
                const float* __restrict__ extra,   // MODE2: g_msg, MODE3: x
                const int*   __restrict__ batch,
                const float* __restrict__ zero,
                __half* __restrict__ outh,
                float* __restrict__ out2)
{
    extern __shared__ __half smem[];

    constexpr int A_L_OFF = BM * ASTR;                       // used iff NPROD==2
    constexpr int B_OFF   = (NPROD == 2 ? 2 : 1) * BM * ASTR;
    constexpr int ST_ELEMS = STAGE_ELEMS_N(NPROD);

    const int tid  = threadIdx.x;
    const int lane = tid & 31, warp = tid >> 5;
    const int warp_m = warp >> 2;
    const int warp_n = warp & 3;
    const int bm = blockIdx.y * BM;
    const int bn = blockIdx.x * BN;

    float acc[4][4][4];
    #pragma unroll
    for (int a = 0; a < 4; a++)
        #pragma unroll
        for (int b = 0; b < 4; b++)
            #pragma unroll
            for (int c = 0; c < 4; c++) acc[a][b][c] = 0.0f;

    const int KT = K / BK;

    auto issue = [&](int s, int k0) {
        __half* base = smem + s * ST_ELEMS;
        #pragma unroll
        for (int i = 0; i < 2; i++) {
            int c = tid + 256 * i;
            int row = c >> 2, coff = (c & 3) * 8;
            int gm = bm + row;
            int p = (gm < M) ? 16 : 0;
            size_t go = (size_t)(p ? gm : 0) * K + k0 + coff;
            cp16(s2u(base + row * ASTR + coff), Agh + go, p);
            if (NPROD == 2)
                cp16(s2u(base + A_L_OFF + row * ASTR + coff), Agl + go, p);
        }
        #pragma unroll
        for (int i = 0; i < 2; i++) {
            int c = tid + 256 * i;
            int row = c >> 4, coff = (c & 15) * 8;
            size_t go = (size_t)(k0 + row) * N + bn + coff;
            cp16(s2u(base + B_OFF + row * BSTR + coff), Bg + go, 16);
        }
    };

    auto compute = [&](int s) {
        __half* base = smem + s * ST_ELEMS;
        #pragma unroll
        for (int kk = 0; kk < 2; kk++) {
            unsigned int ah[4][4], al[4][4], bb[4][2];
            #pragma unroll
            for (int mt = 0; mt < 4; mt++) {
                int row = warp_m * 64 + mt * 16 + (lane & 15);
                int col = kk * 16 + (lane >> 4) * 8;
                LDSM4(ah[mt], s2u(base + row * ASTR + col));
                if (NPROD == 2)
                    LDSM4(al[mt], s2u(base + A_L_OFF + row * ASTR + col));
            }
            #pragma unroll
            for (int nt = 0; nt < 4; nt++) {
                int row = kk * 16 + (lane & 15);
                int col = warp_n * 32 + nt * 8;
                LDSM2T(bb[nt], s2u(base + B_OFF + row * BSTR + col));
            }
            #pragma unroll
            for (int mt = 0; mt < 4; mt++)
                #pragma unroll
                for (int nt = 0; nt < 4; nt++) {
                    MMA_F16(acc[mt][nt], ah[mt], bb[nt]);
                    if (NPROD == 2)
                        MMA_F16(acc[mt][nt], al[mt], bb[nt]);
                }
        }
    };

    // prologue: prefetch STAGES-1 stages
    #pragma unroll
    for (int s = 0; s < STAGES - 1; s++) {
        if (s < KT) issue(s, s * BK);
        asm volatile("cp.async.commit_group;");
    }

    for (int kt = 0; kt < KT; kt++) {
        asm volatile("cp.async.wait_group %0;" :: "n"(STAGES - 2));
        __syncthreads();
        compute(kt % STAGES);
        int next = kt + STAGES - 1;
        if (next < KT) issue(next % STAGES, next * BK);
        asm volatile("cp.async.commit_group;");
    }

    // ---------------- epilogue ----------------
    float scale = 1.0f;
    if (MODE == 2) scale = expf(zero[0]);

    #pragma unroll
    for (int mt = 0; mt < 4; mt++) {
        const int rbase = bm + warp_m * 64 + mt * 16 + (lane >> 2);
        #pragma unroll
        for (int half = 0; half < 2; half++) {
            const int row = rbase + half * 8;
            if (row >= M) continue;
            int g = 0;
            if (MODE == 2) g = batch[row];
            #pragma unroll
            for (int nt = 0; nt < 4; nt++) {
                const int col = bn + warp_n * 32 + nt * 8 + (lane & 3) * 2;
                float v0 = acc[mt][nt][half * 2 + 0] + bias[col];
                float v1 = acc[mt][nt][half * 2 + 1] + bias[col + 1];
                if (MODE == 1 || MODE == 2) {
                    v0 = gelu_exact(v0);
                    v1 = gelu_exact(v1);
                }
                if (MODE == 2) {
                    float2 mv = *(const float2*)(extra + (size_t)g * N + col);
                    v0 += scale * mv.x;
                    v1 += scale * mv.y;
                    *(__half2*)(outh + (size_t)row * N + col) =
                        __halves2half2(__float2half_rn(v0), __float2half_rn(v1));
                } else if (MODE == 3) {
                    float2 xv = *(const float2*)(extra + (size_t)row * N + col);
                    *(float2*)(out2 + (size_t)row * N + col) = make_float2(v0, v1);
                    *(float2*)(C + (size_t)row * N + col) =
                        make_float2(xv.x + v0, xv.y + v1);
                } else {
                    *(float2*)(C + (size_t)row * N + col) = make_float2(v0, v1);
                }
            }
        }
    }
}

// ---------------------------------------------------------------
// LayerNorm + segment pooling; writes xx as single fp16.
// ---------------------------------------------------------------
#define LN_ROWS 32
__global__ __launch_bounds__(128)
void ln_pool_kernel(const float* __restrict__ xraw,
                    __half* __restrict__ xxh,
                    float* __restrict__ pooled, const int* __restrict__ batch)
{
    __shared__ float shs[4], shs2[4];
    const int tid  = threadIdx.x;
    const int lane = tid & 31, warp = tid >> 5;
    const int row0 = blockIdx.x * LN_ROWS;

    float acc0 = 0.f, acc1 = 0.f, acc2 = 0.f, acc3 = 0.f;
    int cur_g = batch[row0];

    for (int r = 0; r < LN_ROWS; r++) {
        const int row = row0 + r;
        float4 v = *(const float4*)(xraw + (size_t)row * WDIM + tid * 4);
        float s  = v.x + v.y + v.z + v.w;
        float s2 = v.x * v.x + v.y * v.y + v.z * v.z + v.w * v.w;
        #pragma unroll
        for (int o = 16; o > 0; o >>= 1) {
            s  += __shfl_xor_sync(0xffffffffu, s,  o);
            s2 += __shfl_xor_sync(0xffffffffu, s2, o);
        }
        if (lane == 0) { shs[warp] = s; shs2[warp] = s2; }
        __syncthreads();
        float sum  = shs[0] + shs[1] + shs[2] + shs[3];
        float sum2 = shs2[0] + shs2[1] + shs2[2] + shs2[3];
        __syncthreads();

        const float mu  = sum * (1.0f / WDIM);
        const float var = sum2 * (1.0f / WDIM) - mu * mu;
        const float rs  = rsqrtf(var + 1e-5f);
        v.x = (v.x - mu) * rs; v.y = (v.y - mu) * rs;
        v.z = (v.z - mu) * rs; v.w = (v.w - mu) * rs;

        size_t o = (size_t)row * WDIM + tid * 4;
        *(__half2*)(xxh + o + 0) =
            __halves2half2(__float2half_rn(v.x), __float2half_rn(v.y));
        *(__half2*)(xxh + o + 2) =
            __halves2half2(__float2half_rn(v.z), __float2half_rn(v.w));

        const int g = batch[row];
        if (g != cur_g) {
            float* p = pooled + (size_t)cur_g * WDIM + tid * 4;
            atomicAdd(p + 0, acc0); atomicAdd(p + 1, acc1);
            atomicAdd(p + 2, acc2); atomicAdd(p + 3, acc3);
            acc0 = acc1 = acc2 = acc3 = 0.f;
            cur_g = g;
        }
        acc0 += v.x; acc1 += v.y; acc2 += v.z; acc3 += v.w;
    }
    float* p = pooled + (size_t)cur_g * WDIM + tid * 4;
    atomicAdd(p + 0, acc0); atomicAdd(p + 1, acc1);
    atomicAdd(p + 2, acc2); atomicAdd(p + 3, acc3);
}

// ---------------------------------------------------------------
extern "C" void kernel_launch(void* const* d_in, const int* in_sizes, int n_in,
                              void* d_out, int out_size)
{
    const float* x      = (const float*)d_in[0];
    const int*   batch  = (const int*)  d_in[1];
    const float* pre_w  = (const float*)d_in[2];
    const float* pre_b  = (const float*)d_in[3];
    const float* mem_w  = (const float*)d_in[4];
    const float* mem_b  = (const float*)d_in[5];
    const float* msg_w  = (const float*)d_in[6];
    const float* msg_b  = (const float*)d_in[7];
    const float* post_w = (const float*)d_in[8];
    const float* post_b = (const float*)d_in[9];
    const float* zero   = (const float*)d_in[10];

    float* out1 = (float*)d_out;
    float* out2 = out1 + (size_t)N_NODES * WDIM;

    float *xraw, *pooled, *msg;
    __half *xh, *xxh, *th, *ph, *pl;
    __half *prew, *memw, *msgw, *postw;
    cudaGetSymbolAddress((void**)&xraw,   g_xraw);
    cudaGetSymbolAddress((void**)&pooled, g_pooled);
    cudaGetSymbolAddress((void**)&msg,    g_msg);
    cudaGetSymbolAddress((void**)&xh,  g_xh);
    cudaGetSymbolAddress((void**)&xxh, g_xxh);
    cudaGetSymbolAddress((void**)&th,  g_th);
    cudaGetSymbolAddress((void**)&ph,  g_ph);   cudaGetSymbolAddress((void**)&pl,  g_pl);
    cudaGetSymbolAddress((void**)&prew,  g_prew);
    cudaGetSymbolAddress((void**)&memw,  g_memw);
    cudaGetSymbolAddress((void**)&msgw,  g_msgw);
    cudaGetSymbolAddress((void**)&postw, g_postw);

    cudaFuncSetAttribute((const void*)gemm_split<0,1>, cudaFuncAttributeMaxDynamicSharedMemorySize, SMEM_BYTES_N(1));
    cudaFuncSetAttribute((const void*)gemm_split<1,2>, cudaFuncAttributeMaxDynamicSharedMemorySize, SMEM_BYTES_N(2));
    cudaFuncSetAttribute((const void*)gemm_split<2,1>, cudaFuncAttributeMaxDynamicSharedMemorySize, SMEM_BYTES_N(1));
    cudaFuncSetAttribute((const void*)gemm_split<3,1>, cudaFuncAttributeMaxDynamicSharedMemorySize, SMEM_BYTES_N(1));

    const dim3 blk(256);
    const int gy = (N_NODES + BM - 1) / BM;           // 1563

    // 0. conversions + zero
    zero_pooled_kernel<<<(NGRAPH * WDIM + 255) / 256, 256>>>();
    {
        int n4 = (int)((size_t)N_NODES * WDIM / 4);
        conv_kernel<<<(n4 + 255) / 256, 256>>>(x, xh, n4);
        conv_kernel<<<(WDIM * WDIM / 4 + 255) / 256, 256>>>(pre_w,  prew,  WDIM * WDIM / 4);
        conv_kernel<<<(WDIM * HDIM / 4 + 255) / 256, 256>>>(mem_w,  memw,  WDIM * HDIM / 4);
        conv_kernel<<<(WDIM * HDIM / 4 + 255) / 256, 256>>>(msg_w,  msgw,  WDIM * HDIM / 4);
        conv_kernel<<<(HDIM * WDIM / 4 + 255) / 256, 256>>>(post_w, postw, HDIM * WDIM / 4);
    }

    // 1. pre GEMM (1-product): xraw = x @ pre_w + pre_b
    gemm_split<0,1><<<dim3(WDIM / BN, gy), blk, SMEM_BYTES_N(1)>>>(
        xh, nullptr, prew, xraw, N_NODES, WDIM, WDIM, pre_b,
        nullptr, nullptr, nullptr, nullptr, nullptr);

    // 2. LayerNorm + segment pooling (-> xxh fp16, pooled fp32)
    ln_pool_kernel<<<N_NODES / LN_ROWS, 128>>>(xraw, xxh, pooled, batch);

    // 3. split pooled (msg keeps 2-product: pooled magnitudes ~10, and it's tiny)
    split_kernel<<<(NGRAPH * WDIM / 4 + 255) / 256, 256>>>(pooled, ph, pl, NGRAPH * WDIM / 4);

    // 4. msg GEMM (2-product): msg = gelu(pooled @ msg_w + msg_b)
    gemm_split<1,2><<<dim3(HDIM / BN, (NGRAPH + BM - 1) / BM), blk, SMEM_BYTES_N(2)>>>(
        ph, pl, msgw, msg, NGRAPH, HDIM, WDIM, msg_b,
        nullptr, nullptr, nullptr, nullptr, nullptr);

    // 5. mem GEMM (1-product): th = gelu(xx @ mem_w + mem_b) + exp(zero)*msg[batch]
    gemm_split<2,1><<<dim3(HDIM / BN, gy), blk, SMEM_BYTES_N(1)>>>(
        xxh, nullptr, memw, nullptr, N_NODES, HDIM, WDIM, mem_b,
        msg, batch, zero, th, nullptr);

    // 6. post GEMM (1-product): y = t @ post_w + post_b; out1 = x + y; out2 = y
    gemm_split<3,1><<<dim3(WDIM / BN, gy), blk, SMEM_BYTES_N(1)>>>(
        th, nullptr, postw, out1, N_NODES, WDIM, HDIM, post_b,
        x, nullptr, nullptr, nullptr, out2);
}